// round 13
// baseline (speedup 1.0000x reference)
#include <cuda_runtime.h>

#define Tn 48
#define Sn 2048
#define Bn 256

__device__ float g_delta[Bn];

typedef unsigned long long ull;

__device__ __forceinline__ ull pack2(float lo, float hi) {
    ull r; asm("mov.b64 %0,{%1,%2};" : "=l"(r) : "f"(lo), "f"(hi)); return r;
}
__device__ __forceinline__ void fma2(ull& a, ull b, ull c) {
    asm("fma.rn.f32x2 %0,%1,%2,%0;" : "+l"(a) : "l"(b), "l"(c));
}
__device__ __forceinline__ ull add2(ull a, ull b) {
    ull r; asm("add.rn.f32x2 %0,%1,%2;" : "=l"(r) : "l"(a), "l"(b)); return r;
}
__device__ __forceinline__ void unpack2(ull v, float& lo, float& hi) {
    asm("mov.b64 {%0,%1},%2;" : "=f"(lo), "=f"(hi) : "l"(v));
}

// ---------------------------------------------------------------------------
// Forward + gold fused: ONE WARP per batch, alpha fully register-resident,
// exchanged per step with 48 SHFLs — no shared memory, no barrier, no LDS/STS
// on the chain (R9's bar.sync+LDS+STS, ~80cyc/step, deleted).
// Lane l holds Sa = alpha[l] and Sb = alpha[32+(l&15)] (lanes 16..31 keep a
// harmless duplicate of lanes 0..15's Sb). Per step each m broadcasts the
// pair (S[2m], S[2m+1]); FFMA2 consumes it directly against
// (E[2m][j], E[2m+1][j]): lo half sums even-k terms, hi half odd-k terms,
// folded once at the end. Each lane produces its two output states with
// 24+24 FFMA2. Exponent-only rescaling as before (exact):
// alpha_i[k] = Esum*ln2 + log(S_i[k]).
// ---------------------------------------------------------------------------
__global__ __launch_bounds__(32)
void crf_fused_kernel(const float* __restrict__ emis,
                      const int*   __restrict__ tags32,
                      const int*   __restrict__ mask,
                      const float* __restrict__ trans,
                      const float* __restrict__ startT,
                      const float* __restrict__ endT)
{
    const unsigned FULL = 0xffffffffu;
    const int b = blockIdx.x;
    const int l = threadIdx.x;          // 0..31
    const int j  = l;                   // first owned state
    const int j2 = 32 + (l & 15);       // second owned state (dup on 16..31)

    // int64-vs-int32 sniff for tags (odd 32-bit words all zero => int64)
    unsigned hw = (unsigned)tags32[2 * l + 1];
    #pragma unroll
    for (int off = 16; off > 0; off >>= 1)
        hw |= __shfl_xor_sync(FULL, hw, off);
    const int is64 = (hw == 0u) ? 1 : 0;

    // E pairs for both owned states: E*[m] = (E[2m][jx], E[2m+1][jx])
    ull EA[24], EB[24];
    #pragma unroll
    for (int m = 0; m < 24; ++m) {
        EA[m] = pack2(__expf(trans[(2 * m) * Tn + j]),
                      __expf(trans[(2 * m + 1) * Tn + j]));
        EB[m] = pack2(__expf(trans[(2 * m) * Tn + j2]),
                      __expf(trans[(2 * m + 1) * Tn + j2]));
    }

    const float* em_b = emis + (size_t)b * Sn * Tn;
    const int*   mk_b = mask + (size_t)b * Sn;

    float Sa = __expf(startT[j]  + em_b[j]);
    float Sb = __expf(startT[j2] + em_b[j2]);
    int Esum = 0;

    // prefetch pipelines (distance 4): exp(emission) for both states + mask
    float FA0 = __expf(em_b[1 * Tn + j]),  FB0 = __expf(em_b[1 * Tn + j2]);
    float FA1 = __expf(em_b[2 * Tn + j]),  FB1 = __expf(em_b[2 * Tn + j2]);
    float FA2 = __expf(em_b[3 * Tn + j]),  FB2 = __expf(em_b[3 * Tn + j2]);
    float FA3 = __expf(em_b[4 * Tn + j]),  FB3 = __expf(em_b[4 * Tn + j2]);
    int m0 = mk_b[1], m1 = mk_b[2], m2 = mk_b[3], m3 = mk_b[4];

    #pragma unroll 2
    for (int i = 1; i < Sn; ++i) {
        const float FA = FA0, FB = FB0;
        const int   mi = m0;

        ull a0 = 0ull, a1 = 0ull, a2 = 0ull, a3 = 0ull;
        ull c0 = 0ull, c1 = 0ull, c2 = 0ull, c3 = 0ull;
        float q0f = 0.f;

        #pragma unroll
        for (int m = 0; m < 24; ++m) {
            float lo, hi;
            if (m < 16) {
                lo = __shfl_sync(FULL, Sa, 2 * m);
                hi = __shfl_sync(FULL, Sa, 2 * m + 1);
            } else {
                lo = __shfl_sync(FULL, Sb, 2 * m - 32);
                hi = __shfl_sync(FULL, Sb, 2 * m - 31);
            }
            if (m == 0) q0f = lo;
            const ull pm = pack2(lo, hi);
            if ((m & 3) == 0) { fma2(a0, pm, EA[m]); fma2(c0, pm, EB[m]); }
            else if ((m & 3) == 1) { fma2(a1, pm, EA[m]); fma2(c1, pm, EB[m]); }
            else if ((m & 3) == 2) { fma2(a2, pm, EA[m]); fma2(c2, pm, EB[m]); }
            else { fma2(a3, pm, EA[m]); fma2(c3, pm, EB[m]); }
        }

        // normalizer from exponent of alpha[0] (exact integer ops)
        const int  xb = __float_as_int(q0f) >> 23;
        const float r = __int_as_float((254 - xb) << 23);

        const ull sA = add2(add2(a0, a1), add2(a2, a3));
        const ull sB = add2(add2(c0, c1), add2(c2, c3));
        float alo, ahi, blo, bhi;
        unpack2(sA, alo, ahi);
        unpack2(sB, blo, bhi);
        const float yA = (alo + ahi) * (FA * r);
        const float yB = (blo + bhi) * (FB * r);

        Sa = mi ? yA : Sa;
        Sb = mi ? yB : Sb;
        Esum += mi ? (xb - 127) : 0;

        // rotate prefetch + fetch i+4 (fully off-chain)
        FA0 = FA1; FA1 = FA2; FA2 = FA3;
        FB0 = FB1; FB1 = FB2; FB2 = FB3;
        m0 = m1; m1 = m2; m2 = m3;
        const int ip = (i + 4 < Sn) ? (i + 4) : (Sn - 1);
        FA3 = __expf(em_b[(size_t)ip * Tn + j]);
        FB3 = __expf(em_b[(size_t)ip * Tn + j2]);
        m3 = mk_b[ip];
    }

    // ---- forward finalize: sum_j S[j]*exp(end[j]) over 48 states ----
    float v = Sa * __expf(endT[j]);
    if (l < 16) v += Sb * __expf(endT[j2]);
    #pragma unroll
    for (int off = 16; off > 0; off >>= 1)
        v += __shfl_xor_sync(FULL, v, off);

    // ---- gold (post-loop, latency-tolerant gathers) ----
    const size_t base = (size_t)b * Sn;
    double gacc = 0.0;
    int cnt = 0;
    for (int i = l; i < Sn; i += 32) {
        const int m = mk_b[i];
        cnt += m;
        if (i >= 1 && m) {
            const size_t ic = base + (size_t)i;
            const int tp = is64 ? tags32[(ic - 1) << 1] : tags32[ic - 1];
            const int tc = is64 ? tags32[ic << 1]       : tags32[ic];
            gacc += (double)trans[tp * Tn + tc]
                  + (double)em_b[(size_t)i * Tn + tc];
        }
    }
    #pragma unroll
    for (int off = 16; off > 0; off >>= 1) {
        gacc += __shfl_down_sync(FULL, gacc, off);
        cnt  += __shfl_down_sync(FULL, cnt,  off);
    }

    if (l == 0) {
        const double fwd = (double)Esum * 0.6931471805599453
                         + (double)logf(v);
        const int t0 = is64 ? tags32[base << 1] : tags32[base];
        double gold = gacc + (double)startT[t0] + (double)em_b[t0];
        const size_t il = base + (size_t)(cnt - 1);
        const int tl = is64 ? tags32[il << 1] : tags32[il];
        gold += (double)endT[tl];
        g_delta[b] = (float)(fwd - gold);
    }
}

// ---------------------------------------------------------------------------
// Final: out = mean(g_delta)
// ---------------------------------------------------------------------------
__global__ __launch_bounds__(256)
void crf_final_kernel(float* __restrict__ out)
{
    __shared__ double sred[256];
    const int t = threadIdx.x;
    sred[t] = (double)g_delta[t];
    __syncthreads();
    for (int s2 = 128; s2 > 0; s2 >>= 1) {
        if (t < s2) sred[t] += sred[t + s2];
        __syncthreads();
    }
    if (t == 0) out[0] = (float)(sred[0] / (double)Bn);
}

extern "C" void kernel_launch(void* const* d_in, const int* in_sizes, int n_in,
                              void* d_out, int out_size)
{
    const float* emis   = (const float*)d_in[0];
    const int*   tags32 = (const int*)d_in[1];   // int32 OR int64 viewed as words
    const int*   mask   = (const int*)d_in[2];
    const float* trans  = (const float*)d_in[3];
    const float* startT = (const float*)d_in[4];
    const float* endT   = (const float*)d_in[5];
    float* out = (float*)d_out;

    crf_fused_kernel<<<Bn, 32>>>(emis, tags32, mask, trans, startT, endT);
    crf_final_kernel<<<1, 256>>>(out);
}